// round 15
// baseline (speedup 1.0000x reference)
#include <cuda_runtime.h>
#include <cstdint>

// Problem constants (fixed by the reference setup).
#define BATCH 16
#define SEQ   4096
#define DIM   256            // floats per frame
#define QUADS (DIM / 4)      // 64 float4 per frame
#define MAXD  7              // durations in [0,8) -> d <= 7

#define CHUNK        16                          // s values per level-1 chunk
#define CHUNKS_PER_BATCH (SEQ / CHUNK)           // 256
#define NCHUNKS      (BATCH * CHUNKS_PER_BATCH)  // 4096
#define SUPERS_PER_BATCH 16
#define NSUPER       (BATCH * SUPERS_PER_BATCH)  // 256
#define NPART_BLOCKS ((NCHUNKS + NSUPER) / 32)   // 136 (1024 thr, 32 warps)
#define ZF_FRAMES    256                         // frames per zero-fill block

#define NCOPY_BLOCKS ((BATCH * SEQ) / 8)         // 8192 (8 warps/block, 1 warp/s)

// Scratch: two-level partial sums of durations.
__device__ int g_part [NCHUNKS];   // [b][c]  sum of 16 durations
__device__ int g_super[NSUPER];    // [b][cs] sum of 256 durations

// ---------------------------------------------------------------------------
// Kernel 1: partials (both levels, straight from dims) + zero-fill.
// Zero-fill is INDEPENDENT of the partials (totals block-reduced from raw
// dims), so it runs in this launch and overlaps; expand then is pure copy.
// ---------------------------------------------------------------------------
__global__ __launch_bounds__(1024) void partial_zf_kernel(
    const int*   __restrict__ dims,  // [B, S]
    float* __restrict__ out,         // [B, T, D]
    int T, int zb_per_batch)
{
    const int tid  = threadIdx.x;
    const int lane = tid & 31;

    if (blockIdx.x < NPART_BLOCKS) {
        // ---- partials role ----
        const int w = blockIdx.x * 32 + (tid >> 5);
        if (w < NCHUNKS) {
            int v = (lane < CHUNK) ? __ldg(dims + (size_t)w * CHUNK + lane) : 0;
            v = __reduce_add_sync(0xFFFFFFFFu, v);
            if (lane == 0) g_part[w] = v;
        } else {
            const int s = w - NCHUNKS;                 // 0..255 == b*16 + cs
            const int4* dp = reinterpret_cast<const int4*>(dims) + (size_t)s * 64;
            const int4 a = __ldg(dp + lane);
            const int4 b = __ldg(dp + lane + 32);
            int v = a.x + a.y + a.z + a.w + b.x + b.y + b.z + b.w;
            v = __reduce_add_sync(0xFFFFFFFFu, v);
            if (lane == 0) g_super[s] = v;
        }
        return;
    }

    // ---- zero-fill role (totals from raw dims; no partials dependency) ----
    const int zb = blockIdx.x - NPART_BLOCKS;
    const int b  = zb / zb_per_batch;
    const int j  = zb - b * zb_per_batch;

    // total_b: block-reduce 4096 durations (1 int4/thread) via warp sums.
    __shared__ int ws[32];
    {
        const int4 q = __ldg(reinterpret_cast<const int4*>(dims + ((size_t)b << 12)) + tid);
        int v = q.x + q.y + q.z + q.w;
        v = __reduce_add_sync(0xFFFFFFFFu, v);
        if (lane == 0) ws[tid >> 5] = v;
    }
    __syncthreads();
    int total = 0;
    #pragma unroll
    for (int i = 0; i < 32; i++) total += ws[i];

    const int base_frame = j * ZF_FRAMES;
    if (base_frame + ZF_FRAMES <= total) return;   // fully covered by copies

    const int base = base_frame * QUADS;           // float4 index within batch
    int end = (base_frame + ZF_FRAMES) * QUADS;
    const int tq = T * QUADS;
    if (end > tq) end = tq;
    const int lo = total * QUADS;                  // first padding float4

    float4* __restrict__ ob = reinterpret_cast<float4*>(out) + (size_t)b * tq;
    const float4 z = make_float4(0.f, 0.f, 0.f, 0.f);
    for (int e = base + tid; e < end; e += 1024)
        if (e >= lo) __stcs(ob + e, z);
}

// ---------------------------------------------------------------------------
// Kernel 2: expand — pure copy, no smem, no __syncthreads, warps independent.
// One warp per (b,s): prologue = R11's one-reduce + 16-lane scan; body =
// predicated straight-line stores (d <= 7), all STG.128s issue back-to-back.
// ---------------------------------------------------------------------------
__global__ __launch_bounds__(256) void expand_kernel(
    const float* __restrict__ x,     // [B, S, D]
    const int*   __restrict__ dims,  // [B, S]
    float* __restrict__ out,         // [B, T, D]
    int T)
{
    const int warp = threadIdx.x >> 5;
    const int lane = threadIdx.x & 31;

    const int gw = blockIdx.x * 8 + warp;        // 0 .. B*SEQ-1 (one warp per s)
    const int b  = gw >> 12;                     // SEQ = 4096
    const int sl = gw & (SEQ - 1);               // s within batch
    const int c  = sl >> 4;                      // chunk index, 0..255
    const int cs = c >> 4;                       // super index, 0..15
    const int cm = c & 15;                       // chunk within super
    const int r  = sl & (CHUNK - 1);             // rank within chunk

    // --- issue all prologue loads up front (latencies overlap) ---
    int p = 0;
    if (lane < 16) {
        if (lane < cs) p = __ldg(g_super + (b << 4) + lane);
    } else {
        const int j = lane - 16;
        if (j < cm)  p = __ldg(g_part + (b << 8) + (cs << 4) + j);
    }
    const int dval = (lane < CHUNK)
        ? __ldg(dims + ((size_t)b << 12) + (c << 4) + lane) : 0;

    // --- prefetch this warp's 1KB source row (2 independent LDG.128) ---
    const float4* __restrict__ src =
        reinterpret_cast<const float4*>(x) + (size_t)gw * QUADS;
    const float4 v0 = __ldg(src + lane);
    const float4 v1 = __ldg(src + lane + 32);

    // --- chunk start ---
    p = __reduce_add_sync(0xFFFFFFFFu, p);

    // --- intra-chunk offset: 16-lane inclusive scan of chunk durations ---
    int sc = dval;
    #pragma unroll
    for (int off = 1; off < CHUNK; off <<= 1) {
        const int n = __shfl_up_sync(0xFFFFFFFFu, sc, off);
        if (lane >= off) sc += n;
    }
    const int d_own = __shfl_sync(0xFFFFFFFFu, dval, r);
    const int incl  = __shfl_sync(0xFFFFFFFFu, sc,   r);
    const int start = p + incl - d_own;          // exclusive prefix for s

    if (d_own == 0) return;

    float4* __restrict__ o = reinterpret_cast<float4*>(out)
                           + ((size_t)b * T + start) * QUADS + lane;

    // Predicated straight-line copies: d <= 7, no loop, stores back-to-back.
    #pragma unroll
    for (int k = 0; k < MAXD; k++) {
        if (k < d_own) {
            __stcs(o + (size_t)k * QUADS,      v0);
            __stcs(o + (size_t)k * QUADS + 32, v1);
        }
    }
}

extern "C" void kernel_launch(void* const* d_in, const int* in_sizes, int n_in,
                              void* d_out, int out_size)
{
    const float* x    = (const float*)d_in[0];   // [B, S, D] float32
    const int*   dims = (const int*)d_in[1];     // [B, S, 1] int32
    float*       out  = (float*)d_out;           // [B, T, D] float32

    const int T = out_size / (BATCH * DIM);
    const int zb_per_batch = (T + ZF_FRAMES - 1) / ZF_FRAMES;

    partial_zf_kernel<<<NPART_BLOCKS + BATCH * zb_per_batch, 1024>>>(
        dims, out, T, zb_per_batch);

    expand_kernel<<<NCOPY_BLOCKS, 256>>>(x, dims, out, T);
}

// round 16
// speedup vs baseline: 1.1312x; 1.1312x over previous
#include <cuda_runtime.h>
#include <cstdint>

// Problem constants (fixed by the reference setup).
#define BATCH 16
#define SEQ   4096
#define DIM   256            // floats per frame
#define QUADS (DIM / 4)      // 64 float4 per frame
#define MAXD  7              // durations in [0,8) -> d <= 7

#define CHUNK        16                          // s values per level-1 chunk
#define CHUNKS_PER_BATCH (SEQ / CHUNK)           // 256
#define NCHUNKS      (BATCH * CHUNKS_PER_BATCH)  // 4096
#define SUPERS_PER_BATCH 16
#define NSUPER       (BATCH * SUPERS_PER_BATCH)  // 256
#define NCOPY_BLOCKS ((BATCH * SEQ) / 8)         // 8192 (8 warps/block, 1 warp/s)
#define ZF_FRAMES    64                          // frames per zero-fill block

// Scratch: two-level partial sums of durations.
__device__ int g_part [NCHUNKS];   // [b][c]  sum of 16 durations
__device__ int g_super[NSUPER];    // [b][cs] sum of 256 durations

// ---------------------------------------------------------------------------
// Kernel 1: partials, both levels, each computed directly from dims
// (no inter-level dependency). One warp per chunk / super-chunk. 136 blocks.
// ---------------------------------------------------------------------------
__global__ __launch_bounds__(1024) void partial_kernel(
    const int* __restrict__ dims)   // [B, S]
{
    const int w    = blockIdx.x * 32 + (threadIdx.x >> 5);
    const int lane = threadIdx.x & 31;

    if (w < NCHUNKS) {
        // level 1: sum of 16 durations
        int v = (lane < CHUNK) ? __ldg(dims + (size_t)w * CHUNK + lane) : 0;
        v = __reduce_add_sync(0xFFFFFFFFu, v);
        if (lane == 0) g_part[w] = v;
    } else {
        // level 2: sum of 256 durations (64 int4, 2 per lane)
        const int s = w - NCHUNKS;                 // 0..255 == b*16 + cs
        const int4* dp = reinterpret_cast<const int4*>(dims) + (size_t)s * 64;
        const int4 a = __ldg(dp + lane);
        const int4 b = __ldg(dp + lane + 32);
        int v = a.x + a.y + a.z + a.w + b.x + b.y + b.z + b.w;
        v = __reduce_add_sync(0xFFFFFFFFu, v);
        if (lane == 0) g_super[s] = v;
    }
}

// ---------------------------------------------------------------------------
// Kernel 2: expand. No shared memory, no __syncthreads — warps independent.
//  - copy blocks [0, 8192): one warp per (b,s). Prologue = one reduce over
//    two-level partials + 16-lane scan; body = predicated straight-line
//    stores (d <= 7), all STG.128s issue back-to-back.
//  - zero-fill tail blocks: total_b = one warp reduce of the 16 super sums
//    (cheap, L2-hit), then pad frames >= total_b with zeros.
// ---------------------------------------------------------------------------
__global__ __launch_bounds__(256) void expand_kernel(
    const float* __restrict__ x,     // [B, S, D]
    const int*   __restrict__ dims,  // [B, S]
    float* __restrict__ out,         // [B, T, D]
    int T, int zb_per_batch)
{
    const int warp = threadIdx.x >> 5;
    const int lane = threadIdx.x & 31;

    if (blockIdx.x < NCOPY_BLOCKS) {
        // ================= copy role =================
        const int gw = blockIdx.x * 8 + warp;        // 0 .. B*SEQ-1 (one warp per s)
        const int b  = gw >> 12;                     // SEQ = 4096
        const int sl = gw & (SEQ - 1);               // s within batch
        const int c  = sl >> 4;                      // chunk index, 0..255
        const int cs = c >> 4;                       // super index, 0..15
        const int cm = c & 15;                       // chunk within super
        const int r  = sl & (CHUNK - 1);             // rank within chunk

        // --- issue all prologue loads up front (latencies overlap) ---
        int p = 0;
        if (lane < 16) {
            if (lane < cs) p = __ldg(g_super + (b << 4) + lane);
        } else {
            const int j = lane - 16;
            if (j < cm)  p = __ldg(g_part + (b << 8) + (cs << 4) + j);
        }
        const int dval = (lane < CHUNK)
            ? __ldg(dims + ((size_t)b << 12) + (c << 4) + lane) : 0;

        // --- prefetch this warp's 1KB source row (2 independent LDG.128) ---
        const float4* __restrict__ src =
            reinterpret_cast<const float4*>(x) + (size_t)gw * QUADS;
        const float4 v0 = __ldg(src + lane);
        const float4 v1 = __ldg(src + lane + 32);

        // --- chunk start ---
        p = __reduce_add_sync(0xFFFFFFFFu, p);

        // --- intra-chunk offset: 16-lane inclusive scan of chunk durations ---
        int sc = dval;
        #pragma unroll
        for (int off = 1; off < CHUNK; off <<= 1) {
            const int n = __shfl_up_sync(0xFFFFFFFFu, sc, off);
            if (lane >= off) sc += n;
        }
        const int d_own = __shfl_sync(0xFFFFFFFFu, dval, r);
        const int incl  = __shfl_sync(0xFFFFFFFFu, sc,   r);
        const int start = p + incl - d_own;          // exclusive prefix for s

        if (d_own == 0) return;

        float4* __restrict__ o = reinterpret_cast<float4*>(out)
                               + ((size_t)b * T + start) * QUADS + lane;

        // Predicated straight-line copies: d <= 7, no loop, stores back-to-back.
        #pragma unroll
        for (int k = 0; k < MAXD; k++) {
            if (k < d_own) {
                __stcs(o + (size_t)k * QUADS,      v0);
                __stcs(o + (size_t)k * QUADS + 32, v1);
            }
        }
        return;
    }

    // ================= zero-fill role (warp-local total, no sync) =================
    {
        const int zb = blockIdx.x - NCOPY_BLOCKS;
        const int b  = zb / zb_per_batch;
        const int j  = zb - b * zb_per_batch;

        // total_b = sum of this batch's 16 super sums.
        int p = (lane < SUPERS_PER_BATCH) ? __ldg(g_super + (b << 4) + lane) : 0;
        const int total = __reduce_add_sync(0xFFFFFFFFu, p);

        const int base_frame = j * ZF_FRAMES;
        if (base_frame + ZF_FRAMES <= total) return;   // fully covered by copies

        const int base = base_frame * QUADS;           // float4 index within batch
        int end = (base_frame + ZF_FRAMES) * QUADS;
        const int tq = T * QUADS;
        if (end > tq) end = tq;
        const int lo = total * QUADS;                  // first padding float4

        float4* __restrict__ ob = reinterpret_cast<float4*>(out) + (size_t)b * tq;
        const float4 z = make_float4(0.f, 0.f, 0.f, 0.f);
        for (int e = base + threadIdx.x; e < end; e += 256)
            if (e >= lo) __stcs(ob + e, z);
    }
}

extern "C" void kernel_launch(void* const* d_in, const int* in_sizes, int n_in,
                              void* d_out, int out_size)
{
    const float* x    = (const float*)d_in[0];   // [B, S, D] float32
    const int*   dims = (const int*)d_in[1];     // [B, S, 1] int32
    float*       out  = (float*)d_out;           // [B, T, D] float32

    const int T = out_size / (BATCH * DIM);
    const int zb_per_batch = (T + ZF_FRAMES - 1) / ZF_FRAMES;

    partial_kernel<<<(NCHUNKS + NSUPER) / 32, 1024>>>(dims);

    const int grid = NCOPY_BLOCKS + BATCH * zb_per_batch;
    expand_kernel<<<grid, 256>>>(x, dims, out, T, zb_per_batch);
}